// round 1
// baseline (speedup 1.0000x reference)
#include <cuda_runtime.h>
#include <math.h>

#define NB 4
#define NC 256
#define HW 4096
#define NHEADS 4
#define HD 64

// Scratch (allocation-free rule: __device__ globals)
__device__ float g_qkv[(size_t)NB * 3 * NC * HW]; // [b][o(768)][hw]
__device__ float g_att[(size_t)NB * NC * HW];     // [b][c][hw]

// ---------------- packed f32x2 helpers (sm_100 FFMA2) ----------------
__device__ __forceinline__ unsigned long long pk2(float lo, float hi) {
    unsigned long long r;
    asm("mov.b64 %0, {%1, %2};" : "=l"(r) : "f"(lo), "f"(hi));
    return r;
}
__device__ __forceinline__ void up2(unsigned long long v, float& lo, float& hi) {
    asm("mov.b64 {%0, %1}, %2;" : "=f"(lo), "=f"(hi) : "l"(v));
}
__device__ __forceinline__ unsigned long long fma2(unsigned long long a,
                                                   unsigned long long b,
                                                   unsigned long long c) {
    unsigned long long d;
    asm("fma.rn.f32x2 %0, %1, %2, %3;" : "=l"(d) : "l"(a), "l"(b), "l"(c));
    return d;
}
__device__ __forceinline__ unsigned long long mul2(unsigned long long a,
                                                   unsigned long long b) {
    unsigned long long d;
    asm("mul.rn.f32x2 %0, %1, %2;" : "=l"(d) : "l"(a), "l"(b));
    return d;
}

// ---------------- GEMM: Y[b][o][i] = sum_c W[o][c] * X[b][c][i] (+bias+res) --------
// BM=64 (blockIdx.y), BN=128 (blockIdx.x), BK=16, 256 threads, 4x8 per-thread tile.
template <int M, bool EPI>
__global__ __launch_bounds__(256) void gemm_k(const float* __restrict__ W,
                                              const float* __restrict__ X,
                                              const float* __restrict__ bias,
                                              const float* __restrict__ R,
                                              float* __restrict__ Y) {
    constexpr int K = 256;
    __shared__ float sA[16 * 65];    // [kk][m], pad 65 -> conflict-free
    __shared__ float sB[16 * 128];   // [kk][j]
    const int b = blockIdx.z;
    const float* Xb = X + (size_t)b * K * HW;
    float* Yb = Y + (size_t)b * M * HW;
    const float* Rb = EPI ? (R + (size_t)b * M * HW) : nullptr;
    const int o0 = blockIdx.y * 64;
    const int i0 = blockIdx.x * 128;
    const int tid = threadIdx.x;
    const int tx = tid & 15, ty = tid >> 4;

    float acc[4][8];
#pragma unroll
    for (int r = 0; r < 4; r++)
#pragma unroll
        for (int c = 0; c < 8; c++) acc[r][c] = 0.f;

    for (int c0 = 0; c0 < K; c0 += 16) {
#pragma unroll
        for (int l = 0; l < 4; l++) {
            int idx = tid + l * 256;
            int m = idx >> 4, kk = idx & 15;
            sA[kk * 65 + m] = W[(size_t)(o0 + m) * K + c0 + kk];
        }
#pragma unroll
        for (int l = 0; l < 2; l++) {
            int e = (tid + l * 256) * 4;
            int kk = e >> 7, j = e & 127;
            *(float4*)&sB[kk * 128 + j] =
                *(const float4*)&Xb[(size_t)(c0 + kk) * HW + i0 + j];
        }
        __syncthreads();
#pragma unroll
        for (int kk = 0; kk < 16; kk++) {
            float aa[4];
#pragma unroll
            for (int r = 0; r < 4; r++) aa[r] = sA[kk * 65 + ty * 4 + r];
            float4 b0 = *(float4*)&sB[kk * 128 + tx * 8];
            float4 b1 = *(float4*)&sB[kk * 128 + tx * 8 + 4];
            float bb[8] = {b0.x, b0.y, b0.z, b0.w, b1.x, b1.y, b1.z, b1.w};
#pragma unroll
            for (int r = 0; r < 4; r++)
#pragma unroll
                for (int c = 0; c < 8; c++) acc[r][c] = fmaf(aa[r], bb[c], acc[r][c]);
        }
        __syncthreads();
    }
#pragma unroll
    for (int r = 0; r < 4; r++) {
        int o = o0 + ty * 4 + r;
        size_t base = (size_t)o * HW + i0 + tx * 8;
        float4 v0, v1;
        if (EPI) {
            float add = bias[o];
            float4 r0 = *(const float4*)&Rb[base];
            float4 r1 = *(const float4*)&Rb[base + 4];
            v0.x = acc[r][0] + add + r0.x;
            v0.y = acc[r][1] + add + r0.y;
            v0.z = acc[r][2] + add + r0.z;
            v0.w = acc[r][3] + add + r0.w;
            v1.x = acc[r][4] + add + r1.x;
            v1.y = acc[r][5] + add + r1.y;
            v1.z = acc[r][6] + add + r1.z;
            v1.w = acc[r][7] + add + r1.w;
        } else {
            v0.x = acc[r][0]; v0.y = acc[r][1]; v0.z = acc[r][2]; v0.w = acc[r][3];
            v1.x = acc[r][4]; v1.y = acc[r][5]; v1.z = acc[r][6]; v1.w = acc[r][7];
        }
        *(float4*)&Yb[base] = v0;
        *(float4*)&Yb[base + 4] = v1;
    }
}

// ---------------- Flash attention ----------------
// Grid: (HW/128, NB*NHEADS). 256 threads. Q tile 128 rows, K tile 128 cols.
// S-phase thread map: rows i = ty*8+ii, cols j = tx*8+jj (8x8 per thread).
// O-phase thread map: rows i = tx*8+ii, cols dd = ty*4+cc (8x4 per thread).
// sP stored transposed [j][i] with XOR chunk swizzle; softmax state in SMEM.
#define ATT_SMEM ((3 * 64 * 128 + 128 * 128 + 3 * 128) * sizeof(float))

__global__ __launch_bounds__(256, 1) void attn_k() {
    extern __shared__ float sm[];
    float* sQ = sm;                  // [dd][i]  64x128 (pre-scaled)
    float* sK = sQ + 64 * 128;       // [dd][j]
    float* sV = sK + 64 * 128;       // [dd][j]
    float* sP = sV + 64 * 128;       // [j][i] swizzled
    float* sM = sP + 128 * 128;      // running max [128]
    float* sL = sM + 128;            // running sum [128]
    float* sF = sL + 128;            // per-tile rescale [128]

    const int bh = blockIdx.y;
    const int b = bh >> 2, h = bh & 3;
    const float* Qb = g_qkv + ((size_t)b * 768 + h * 64) * HW;
    const float* Kb = Qb + (size_t)256 * HW;
    const float* Vb = Qb + (size_t)512 * HW;
    const int i0 = blockIdx.x * 128;
    const int tid = threadIdx.x;
    const int tx = tid & 15, ty = tid >> 4;

    for (int e = tid * 4; e < 64 * 128; e += 1024) {
        int dd = e >> 7, i = e & 127;
        float4 v = *(const float4*)&Qb[(size_t)dd * HW + i0 + i];
        v.x *= 0.125f; v.y *= 0.125f; v.z *= 0.125f; v.w *= 0.125f;  // fold scale
        *(float4*)&sQ[e] = v;
    }
    if (tid < 128) { sM[tid] = -INFINITY; sL[tid] = 0.f; }

    unsigned long long o2[4][4];  // packed O accum: rows (tx*8+2ip, +1), col ty*4+cc
#pragma unroll
    for (int ip = 0; ip < 4; ip++)
#pragma unroll
        for (int cc = 0; cc < 4; cc++) o2[ip][cc] = 0ull;

    __syncthreads();

    for (int kt = 0; kt < 32; kt++) {
        const int j0 = kt * 128;
        for (int e = tid * 4; e < 64 * 128; e += 1024) {
            int dd = e >> 7, j = e & 127;
            *(float4*)&sK[e] = *(const float4*)&Kb[(size_t)dd * HW + j0 + j];
            *(float4*)&sV[e] = *(const float4*)&Vb[(size_t)dd * HW + j0 + j];
        }
        __syncthreads();

        // ---- S = (Q*scale)^T K, 8x8 per thread, packed f32x2 over j-pairs ----
        unsigned long long acc2[8][4];
#pragma unroll
        for (int ii = 0; ii < 8; ii++)
#pragma unroll
            for (int jp = 0; jp < 4; jp++) acc2[ii][jp] = 0ull;

#pragma unroll 4
        for (int dd = 0; dd < 64; dd++) {
            float4 q0 = *(float4*)&sQ[dd * 128 + ty * 8];
            float4 q1 = *(float4*)&sQ[dd * 128 + ty * 8 + 4];
            float4 k0 = *(float4*)&sK[dd * 128 + tx * 8];
            float4 k1 = *(float4*)&sK[dd * 128 + tx * 8 + 4];
            unsigned long long k2[4] = {pk2(k0.x, k0.y), pk2(k0.z, k0.w),
                                        pk2(k1.x, k1.y), pk2(k1.z, k1.w)};
            float qa[8] = {q0.x, q0.y, q0.z, q0.w, q1.x, q1.y, q1.z, q1.w};
#pragma unroll
            for (int ii = 0; ii < 8; ii++) {
                unsigned long long q2 = pk2(qa[ii], qa[ii]);
#pragma unroll
                for (int jp = 0; jp < 4; jp++)
                    acc2[ii][jp] = fma2(q2, k2[jp], acc2[ii][jp]);
            }
        }

        float p[8][8];
#pragma unroll
        for (int ii = 0; ii < 8; ii++)
#pragma unroll
            for (int jp = 0; jp < 4; jp++)
                up2(acc2[ii][jp], p[ii][2 * jp], p[ii][2 * jp + 1]);

        // ---- online softmax ----
        float rm[8];
#pragma unroll
        for (int ii = 0; ii < 8; ii++) {
            float m = p[ii][0];
#pragma unroll
            for (int jj = 1; jj < 8; jj++) m = fmaxf(m, p[ii][jj]);
            rm[ii] = m;
        }
#pragma unroll
        for (int d = 1; d < 16; d <<= 1)
#pragma unroll
            for (int ii = 0; ii < 8; ii++)
                rm[ii] = fmaxf(rm[ii], __shfl_xor_sync(0xffffffffu, rm[ii], d));
        if (tx == 0) {
#pragma unroll
            for (int ii = 0; ii < 8; ii++) {
                int i = ty * 8 + ii;
                float mo = sM[i];
                float mn = fmaxf(mo, rm[ii]);
                sM[i] = mn;
                sF[i] = __expf(mo - mn);
            }
        }
        __syncthreads();

        float rs[8];
#pragma unroll
        for (int ii = 0; ii < 8; ii++) {
            float mn = sM[ty * 8 + ii];
            float s = 0.f;
#pragma unroll
            for (int jj = 0; jj < 8; jj++) {
                p[ii][jj] = __expf(p[ii][jj] - mn);
                s += p[ii][jj];
            }
            rs[ii] = s;
        }
        // write P transposed+swizzled: row j = tx*8+jj, cols i0c = ty*8..+8
        const int sw = tx & 7;
#pragma unroll
        for (int jj = 0; jj < 8; jj++) {
            int rowb = (tx * 8 + jj) * 128;
            float4 fa = make_float4(p[0][jj], p[1][jj], p[2][jj], p[3][jj]);
            float4 fb = make_float4(p[4][jj], p[5][jj], p[6][jj], p[7][jj]);
            *(float4*)&sP[rowb + (((ty * 2 + 0) ^ sw) << 2)] = fa;
            *(float4*)&sP[rowb + (((ty * 2 + 1) ^ sw) << 2)] = fb;
        }
#pragma unroll
        for (int d = 1; d < 16; d <<= 1)
#pragma unroll
            for (int ii = 0; ii < 8; ii++)
                rs[ii] += __shfl_xor_sync(0xffffffffu, rs[ii], d);
        if (tx == 0) {
#pragma unroll
            for (int ii = 0; ii < 8; ii++) {
                int i = ty * 8 + ii;
                sL[i] = sL[i] * sF[i] + rs[ii];
            }
        }
        __syncthreads();

        // ---- O rescale + accumulate O += P @ V^T ----
        {
            float4 f0 = *(float4*)&sF[tx * 8];
            float4 f1 = *(float4*)&sF[tx * 8 + 4];
            float fr[8] = {f0.x, f0.y, f0.z, f0.w, f1.x, f1.y, f1.z, f1.w};
#pragma unroll
            for (int ip = 0; ip < 4; ip++) {
                unsigned long long f2 = pk2(fr[2 * ip], fr[2 * ip + 1]);
#pragma unroll
                for (int cc = 0; cc < 4; cc++) o2[ip][cc] = mul2(o2[ip][cc], f2);
            }
        }
#pragma unroll 2
        for (int j = 0; j < 128; j++) {
            int rowb = j * 128;
            int swj = (j >> 3) & 7;
            float4 pa = *(float4*)&sP[rowb + (((tx * 2 + 0) ^ swj) << 2)];
            float4 pb = *(float4*)&sP[rowb + (((tx * 2 + 1) ^ swj) << 2)];
            unsigned long long p2[4] = {pk2(pa.x, pa.y), pk2(pa.z, pa.w),
                                        pk2(pb.x, pb.y), pk2(pb.z, pb.w)};
#pragma unroll
            for (int cc = 0; cc < 4; cc++) {
                float v = sV[(ty * 4 + cc) * 128 + j];
                unsigned long long v2 = pk2(v, v);
#pragma unroll
                for (int ip = 0; ip < 4; ip++)
                    o2[ip][cc] = fma2(p2[ip], v2, o2[ip][cc]);
            }
        }
        __syncthreads();
    }

    // ---- epilogue: divide by l, write g_att[b][h*64+dd][i] ----
    float4 l0 = *(float4*)&sL[tx * 8];
    float4 l1 = *(float4*)&sL[tx * 8 + 4];
    float inv[8] = {1.f / l0.x, 1.f / l0.y, 1.f / l0.z, 1.f / l0.w,
                    1.f / l1.x, 1.f / l1.y, 1.f / l1.z, 1.f / l1.w};
#pragma unroll
    for (int cc = 0; cc < 4; cc++) {
        float ov[8];
#pragma unroll
        for (int ip = 0; ip < 4; ip++) up2(o2[ip][cc], ov[2 * ip], ov[2 * ip + 1]);
#pragma unroll
        for (int ii = 0; ii < 8; ii++) ov[ii] *= inv[ii];
        size_t base = ((size_t)b * 256 + h * 64 + ty * 4 + cc) * HW + i0 + tx * 8;
        *(float4*)&g_att[base] = make_float4(ov[0], ov[1], ov[2], ov[3]);
        *(float4*)&g_att[base + 4] = make_float4(ov[4], ov[5], ov[6], ov[7]);
    }
}

// ---------------- launch ----------------
extern "C" void kernel_launch(void* const* d_in, const int* in_sizes, int n_in,
                              void* d_out, int out_size) {
    (void)in_sizes; (void)n_in; (void)out_size;
    const float* x     = (const float*)d_in[0];
    const float* w_qkv = (const float*)d_in[1];
    const float* w_out = (const float*)d_in[2];
    const float* b_out = (const float*)d_in[3];
    float* out = (float*)d_out;

    float* qkv_p = nullptr;
    float* att_p = nullptr;
    cudaGetSymbolAddress((void**)&qkv_p, g_qkv);
    cudaGetSymbolAddress((void**)&att_p, g_att);

    cudaFuncSetAttribute(attn_k, cudaFuncAttributeMaxDynamicSharedMemorySize,
                         (int)ATT_SMEM);

    // 1) qkv = w_qkv @ x   (per batch)
    gemm_k<768, false><<<dim3(32, 12, 4), 256>>>(w_qkv, x, nullptr, nullptr, qkv_p);
    // 2) flash attention
    attn_k<<<dim3(32, 16), 256, ATT_SMEM>>>();
    // 3) out = x + w_out @ att + b_out
    gemm_k<256, true><<<dim3(32, 4, 4), 256>>>(w_out, att_p, b_out, x, out);
}

// round 2
// speedup vs baseline: 2.5565x; 2.5565x over previous
#include <cuda_runtime.h>
#include <math.h>

#define NB 4
#define NC 256
#define HW 4096
#define NHEADS 4
#define HD 64

// Scratch (allocation-free rule: __device__ globals)
__device__ float g_qkv[(size_t)NB * 3 * NC * HW]; // [b][o(768)][hw]
__device__ float g_att[(size_t)NB * NC * HW];     // [b][c][hw]

// ---------------- helpers ----------------
__device__ __forceinline__ float to_tf32(float x) {
    unsigned u;
    asm("cvt.rna.tf32.f32 %0, %1;" : "=r"(u) : "f"(x));
    return __uint_as_float(u);
}
__device__ __forceinline__ float ex2f(float x) {
    float y;
    asm("ex2.approx.f32 %0, %1;" : "=f"(y) : "f"(x));
    return y;
}
// D += A(16x8 tf32) * B(8x8 tf32), fp32 accumulate
__device__ __forceinline__ void mma_tf32(float c[4], const float a[4], float b0,
                                         float b1) {
    asm volatile(
        "mma.sync.aligned.m16n8k8.row.col.f32.tf32.tf32.f32 "
        "{%0,%1,%2,%3}, {%4,%5,%6,%7}, {%8,%9}, {%0,%1,%2,%3};"
        : "+f"(c[0]), "+f"(c[1]), "+f"(c[2]), "+f"(c[3])
        : "r"(__float_as_uint(a[0])), "r"(__float_as_uint(a[1])),
          "r"(__float_as_uint(a[2])), "r"(__float_as_uint(a[3])),
          "r"(__float_as_uint(b0)), "r"(__float_as_uint(b1)));
}

// ---------------- GEMM: Y[b][o][i] = sum_c W[o][c] * X[b][c][i] (+bias+res) ----
template <int M, bool EPI>
__global__ __launch_bounds__(256) void gemm_k(const float* __restrict__ W,
                                              const float* __restrict__ X,
                                              const float* __restrict__ bias,
                                              const float* __restrict__ R,
                                              float* __restrict__ Y) {
    constexpr int K = 256;
    __shared__ float sA[16 * 65];
    __shared__ float sB[16 * 128];
    const int b = blockIdx.z;
    const float* Xb = X + (size_t)b * K * HW;
    float* Yb = Y + (size_t)b * M * HW;
    const float* Rb = EPI ? (R + (size_t)b * M * HW) : nullptr;
    const int o0 = blockIdx.y * 64;
    const int i0 = blockIdx.x * 128;
    const int tid = threadIdx.x;
    const int tx = tid & 15, ty = tid >> 4;

    float acc[4][8];
#pragma unroll
    for (int r = 0; r < 4; r++)
#pragma unroll
        for (int c = 0; c < 8; c++) acc[r][c] = 0.f;

    for (int c0 = 0; c0 < K; c0 += 16) {
#pragma unroll
        for (int l = 0; l < 4; l++) {
            int idx = tid + l * 256;
            int m = idx >> 4, kk = idx & 15;
            sA[kk * 65 + m] = W[(size_t)(o0 + m) * K + c0 + kk];
        }
#pragma unroll
        for (int l = 0; l < 2; l++) {
            int e = (tid + l * 256) * 4;
            int kk = e >> 7, j = e & 127;
            *(float4*)&sB[kk * 128 + j] =
                *(const float4*)&Xb[(size_t)(c0 + kk) * HW + i0 + j];
        }
        __syncthreads();
#pragma unroll
        for (int kk = 0; kk < 16; kk++) {
            float aa[4];
#pragma unroll
            for (int r = 0; r < 4; r++) aa[r] = sA[kk * 65 + ty * 4 + r];
            float4 b0 = *(float4*)&sB[kk * 128 + tx * 8];
            float4 b1 = *(float4*)&sB[kk * 128 + tx * 8 + 4];
            float bb[8] = {b0.x, b0.y, b0.z, b0.w, b1.x, b1.y, b1.z, b1.w};
#pragma unroll
            for (int r = 0; r < 4; r++)
#pragma unroll
                for (int c = 0; c < 8; c++) acc[r][c] = fmaf(aa[r], bb[c], acc[r][c]);
        }
        __syncthreads();
    }
#pragma unroll
    for (int r = 0; r < 4; r++) {
        int o = o0 + ty * 4 + r;
        size_t base = (size_t)o * HW + i0 + tx * 8;
        float4 v0, v1;
        if (EPI) {
            float add = bias[o];
            float4 r0 = *(const float4*)&Rb[base];
            float4 r1 = *(const float4*)&Rb[base + 4];
            v0.x = acc[r][0] + add + r0.x;
            v0.y = acc[r][1] + add + r0.y;
            v0.z = acc[r][2] + add + r0.z;
            v0.w = acc[r][3] + add + r0.w;
            v1.x = acc[r][4] + add + r1.x;
            v1.y = acc[r][5] + add + r1.y;
            v1.z = acc[r][6] + add + r1.z;
            v1.w = acc[r][7] + add + r1.w;
        } else {
            v0.x = acc[r][0]; v0.y = acc[r][1]; v0.z = acc[r][2]; v0.w = acc[r][3];
            v1.x = acc[r][4]; v1.y = acc[r][5]; v1.z = acc[r][6]; v1.w = acc[r][7];
        }
        *(float4*)&Yb[base] = v0;
        *(float4*)&Yb[base + 4] = v1;
    }
}

// ---------------- Flash attention with tf32 mma.sync ----------------
// Grid (32, 16), 256 threads = 8 warps. Warp w owns Q rows [w*16, w*16+16).
// SMEM: sK [64][136], sV [64][132], sP [128][132] (Q staged in sP region).
#define SK_PITCH 136
#define SV_PITCH 132
#define SP_PITCH 132
#define SK_FLOATS (64 * SK_PITCH)
#define SV_FLOATS (64 * SV_PITCH)
#define SP_FLOATS (128 * SP_PITCH)
#define ATT_SMEM ((SK_FLOATS + SV_FLOATS + SP_FLOATS) * sizeof(float))

__global__ __launch_bounds__(256, 1) void attn_k() {
    extern __shared__ float sm[];
    float* sK = sm;
    float* sV = sK + SK_FLOATS;
    float* sP = sV + SV_FLOATS;
    float* sQst = sP;  // Q staging aliases sP (prologue only), pitch SK_PITCH

    const int bh = blockIdx.y;
    const int b = bh >> 2, h = bh & 3;
    const float* Qb = g_qkv + ((size_t)b * 768 + h * 64) * HW;
    const float* Kb = Qb + (size_t)256 * HW;
    const float* Vb = Qb + (size_t)512 * HW;
    const int i0 = blockIdx.x * 128;
    const int tid = threadIdx.x;
    const int warp = tid >> 5, lane = tid & 31;
    const int g = lane >> 2, t = lane & 3;  // groupID / threadInGroup
    const int iw = warp * 16;

    const float QSCALE = 0.125f * 1.4426950408889634f;  // d^-0.5 * log2(e)

    // ---- stage Q (scaled, tf32) into sQst [d][SK_PITCH] ----
    for (int e = tid * 4; e < 64 * 128; e += 1024) {
        int d = e >> 7, i = e & 127;
        float4 v = *(const float4*)&Qb[(size_t)d * HW + i0 + i];
        v.x = to_tf32(v.x * QSCALE); v.y = to_tf32(v.y * QSCALE);
        v.z = to_tf32(v.z * QSCALE); v.w = to_tf32(v.w * QSCALE);
        *(float4*)&sQst[d * SK_PITCH + i] = v;
    }
    __syncthreads();

    // ---- extract persistent Q fragments: qa[ks][0..3] ----
    float qa[8][4];
#pragma unroll
    for (int ks = 0; ks < 8; ks++) {
        qa[ks][0] = sQst[(ks * 8 + t) * SK_PITCH + iw + g];
        qa[ks][1] = sQst[(ks * 8 + t) * SK_PITCH + iw + g + 8];
        qa[ks][2] = sQst[(ks * 8 + t + 4) * SK_PITCH + iw + g];
        qa[ks][3] = sQst[(ks * 8 + t + 4) * SK_PITCH + iw + g + 8];
    }

    float o[8][4];
#pragma unroll
    for (int dt = 0; dt < 8; dt++)
#pragma unroll
        for (int r = 0; r < 4; r++) o[dt][r] = 0.f;
    float m0 = -INFINITY, m1 = -INFINITY, l0 = 0.f, l1 = 0.f;

    for (int kt = 0; kt < 32; kt++) {
        const int j0 = kt * 128;
        __syncthreads();  // protect sK/sV/sP from previous iter readers
        // ---- stage K, V (tf32) ----
        for (int e = tid * 4; e < 64 * 128; e += 1024) {
            int d = e >> 7, j = e & 127;
            float4 k4 = *(const float4*)&Kb[(size_t)d * HW + j0 + j];
            k4.x = to_tf32(k4.x); k4.y = to_tf32(k4.y);
            k4.z = to_tf32(k4.z); k4.w = to_tf32(k4.w);
            *(float4*)&sK[d * SK_PITCH + j] = k4;
            float4 v4 = *(const float4*)&Vb[(size_t)d * HW + j0 + j];
            v4.x = to_tf32(v4.x); v4.y = to_tf32(v4.y);
            v4.z = to_tf32(v4.z); v4.w = to_tf32(v4.w);
            *(float4*)&sV[d * SV_PITCH + j] = v4;
        }
        __syncthreads();

        // ---- S = Q K^T : 16 n8-tiles, k over d (8 steps) ----
        float c[16][4];
#pragma unroll
        for (int jt = 0; jt < 16; jt++)
#pragma unroll
            for (int r = 0; r < 4; r++) c[jt][r] = 0.f;
#pragma unroll
        for (int ks = 0; ks < 8; ks++) {
#pragma unroll
            for (int jt = 0; jt < 16; jt++) {
                float b0 = sK[(ks * 8 + t) * SK_PITCH + jt * 8 + g];
                float b1 = sK[(ks * 8 + t + 4) * SK_PITCH + jt * 8 + g];
                mma_tf32(c[jt], qa[ks], b0, b1);
            }
        }

        // ---- online softmax (log2 domain; scale folded into Q) ----
        float mx0 = c[0][0], mx1 = c[0][2];
#pragma unroll
        for (int jt = 0; jt < 16; jt++) {
            mx0 = fmaxf(mx0, fmaxf(c[jt][0], c[jt][1]));
            mx1 = fmaxf(mx1, fmaxf(c[jt][2], c[jt][3]));
        }
        mx0 = fmaxf(mx0, __shfl_xor_sync(0xffffffffu, mx0, 1));
        mx0 = fmaxf(mx0, __shfl_xor_sync(0xffffffffu, mx0, 2));
        mx1 = fmaxf(mx1, __shfl_xor_sync(0xffffffffu, mx1, 1));
        mx1 = fmaxf(mx1, __shfl_xor_sync(0xffffffffu, mx1, 2));
        float nm0 = fmaxf(m0, mx0), nm1 = fmaxf(m1, mx1);
        float r0 = ex2f(m0 - nm0), r1 = ex2f(m1 - nm1);
        float rs0 = 0.f, rs1 = 0.f;
#pragma unroll
        for (int jt = 0; jt < 16; jt++) {
            c[jt][0] = ex2f(c[jt][0] - nm0);
            c[jt][1] = ex2f(c[jt][1] - nm0);
            c[jt][2] = ex2f(c[jt][2] - nm1);
            c[jt][3] = ex2f(c[jt][3] - nm1);
            rs0 += c[jt][0] + c[jt][1];
            rs1 += c[jt][2] + c[jt][3];
        }
        rs0 += __shfl_xor_sync(0xffffffffu, rs0, 1);
        rs0 += __shfl_xor_sync(0xffffffffu, rs0, 2);
        rs1 += __shfl_xor_sync(0xffffffffu, rs1, 1);
        rs1 += __shfl_xor_sync(0xffffffffu, rs1, 2);
        l0 = l0 * r0 + rs0;
        l1 = l1 * r1 + rs1;
        m0 = nm0; m1 = nm1;
#pragma unroll
        for (int dt = 0; dt < 8; dt++) {
            o[dt][0] *= r0; o[dt][1] *= r0;
            o[dt][2] *= r1; o[dt][3] *= r1;
        }

        // ---- write P (tf32) to sP [i][SP_PITCH], warp-private rows ----
#pragma unroll
        for (int jt = 0; jt < 16; jt++) {
            float2 p01 = make_float2(to_tf32(c[jt][0]), to_tf32(c[jt][1]));
            float2 p23 = make_float2(to_tf32(c[jt][2]), to_tf32(c[jt][3]));
            *(float2*)&sP[(iw + g) * SP_PITCH + jt * 8 + 2 * t] = p01;
            *(float2*)&sP[(iw + g + 8) * SP_PITCH + jt * 8 + 2 * t] = p23;
        }
        __syncwarp();

        // ---- O += P V : k over j (16 steps), 8 n8-tiles over d ----
#pragma unroll 4
        for (int ks2 = 0; ks2 < 16; ks2++) {
            float a[4];
            a[0] = sP[(iw + g) * SP_PITCH + ks2 * 8 + t];
            a[1] = sP[(iw + g + 8) * SP_PITCH + ks2 * 8 + t];
            a[2] = sP[(iw + g) * SP_PITCH + ks2 * 8 + t + 4];
            a[3] = sP[(iw + g + 8) * SP_PITCH + ks2 * 8 + t + 4];
#pragma unroll
            for (int dt = 0; dt < 8; dt++) {
                float b0 = sV[(dt * 8 + g) * SV_PITCH + ks2 * 8 + t];
                float b1 = sV[(dt * 8 + g) * SV_PITCH + ks2 * 8 + t + 4];
                mma_tf32(o[dt], a, b0, b1);
            }
        }
    }

    // ---- epilogue: O/l -> g_att[b][h*64+d][i0+i] ----
    float inv0 = 1.f / l0, inv1 = 1.f / l1;
    const size_t cb = ((size_t)b * 256 + h * 64);
#pragma unroll
    for (int dt = 0; dt < 8; dt++) {
        int d0 = dt * 8 + 2 * t;
        size_t r0a = (cb + d0) * HW + i0 + iw + g;
        size_t r1a = (cb + d0 + 1) * HW + i0 + iw + g;
        g_att[r0a] = o[dt][0] * inv0;
        g_att[r1a] = o[dt][1] * inv0;
        g_att[r0a + 8] = o[dt][2] * inv1;
        g_att[r1a + 8] = o[dt][3] * inv1;
    }
}

// ---------------- launch ----------------
extern "C" void kernel_launch(void* const* d_in, const int* in_sizes, int n_in,
                              void* d_out, int out_size) {
    (void)in_sizes; (void)n_in; (void)out_size;
    const float* x     = (const float*)d_in[0];
    const float* w_qkv = (const float*)d_in[1];
    const float* w_out = (const float*)d_in[2];
    const float* b_out = (const float*)d_in[3];
    float* out = (float*)d_out;

    float* qkv_p = nullptr;
    float* att_p = nullptr;
    cudaGetSymbolAddress((void**)&qkv_p, g_qkv);
    cudaGetSymbolAddress((void**)&att_p, g_att);

    cudaFuncSetAttribute(attn_k, cudaFuncAttributeMaxDynamicSharedMemorySize,
                         (int)ATT_SMEM);

    gemm_k<768, false><<<dim3(32, 12, 4), 256>>>(w_qkv, x, nullptr, nullptr, qkv_p);
    attn_k<<<dim3(32, 16), 256, ATT_SMEM>>>();
    gemm_k<256, true><<<dim3(32, 4, 4), 256>>>(w_out, att_p, b_out, x, out);
}

// round 4
// speedup vs baseline: 3.7317x; 1.4597x over previous
#include <cuda_runtime.h>
#include <math.h>

#define NB 4
#define NC 256
#define HW 4096
#define NHEADS 4
#define HD 64

// Scratch (allocation-free rule: __device__ globals)
__device__ float g_qkv[(size_t)NB * 3 * NC * HW]; // [b][o(768)][hw]
__device__ float g_att[(size_t)NB * NC * HW];     // [b][c][hw]

// ---------------- helpers ----------------
__device__ __forceinline__ float to_tf32(float x) {
    unsigned u;
    asm("cvt.rna.tf32.f32 %0, %1;" : "=r"(u) : "f"(x));
    return __uint_as_float(u);
}
__device__ __forceinline__ float ex2f(float x) {
    float y;
    asm("ex2.approx.f32 %0, %1;" : "=f"(y) : "f"(x));
    return y;
}
// D += A(16x8 tf32) * B(8x8 tf32), fp32 accumulate
__device__ __forceinline__ void mma_tf32(float c[4], const float a[4], float b0,
                                         float b1) {
    asm volatile(
        "mma.sync.aligned.m16n8k8.row.col.f32.tf32.tf32.f32 "
        "{%0,%1,%2,%3}, {%4,%5,%6,%7}, {%8,%9}, {%0,%1,%2,%3};"
        : "+f"(c[0]), "+f"(c[1]), "+f"(c[2]), "+f"(c[3])
        : "r"(__float_as_uint(a[0])), "r"(__float_as_uint(a[1])),
          "r"(__float_as_uint(a[2])), "r"(__float_as_uint(a[3])),
          "r"(__float_as_uint(b0)), "r"(__float_as_uint(b1)));
}
__device__ __forceinline__ void cpa16(float* dst, const float* src) {
    unsigned d = (unsigned)__cvta_generic_to_shared(dst);
    asm volatile("cp.async.cg.shared.global [%0], [%1], 16;" ::"r"(d), "l"(src));
}
#define CP_COMMIT asm volatile("cp.async.commit_group;")
#define CP_WAIT(n) asm volatile("cp.async.wait_group %0;" ::"n"(n))

// ================ tf32 tensor-core GEMM ================
// Y[b][o][i] = sum_c W[o][c] * X[b][c][i] (+ bias + residual)
// CTA tile 128(M)x128(N), BK=32, 8 warps (4m x 2n), warp tile 32x64.
// sA [k? no: [m][k]] pitch 36, sB [k][n] pitch 136, both double-buffered.
#define GA_PITCH 36
#define GB_PITCH 136
#define GA_FLOATS (128 * GA_PITCH)
#define GB_FLOATS (32 * GB_PITCH)
#define GEMM_SMEM ((2 * GA_FLOATS + 2 * GB_FLOATS) * sizeof(float))

template <int M, bool EPI>
__global__ __launch_bounds__(256, 2) void gemm_tc(const float* __restrict__ W,
                                                  const float* __restrict__ X,
                                                  const float* __restrict__ bias,
                                                  const float* __restrict__ R,
                                                  float* __restrict__ Y) {
    extern __shared__ float sm[];
    float* sA = sm;                  // [2][128][36]
    float* sB = sm + 2 * GA_FLOATS;  // [2][32][136]
    const int b = blockIdx.z;
    const float* Xb = X + (size_t)b * 256 * HW;
    float* Yb = Y + (size_t)b * M * HW;
    const float* Rb = EPI ? (R + (size_t)b * M * HW) : nullptr;
    const int o0 = blockIdx.y * 128;
    const int i0 = blockIdx.x * 128;
    const int tid = threadIdx.x, warp = tid >> 5, lane = tid & 31;
    const int g = lane >> 2, t = lane & 3;
    const int wm = (warp >> 1) * 32, wn = (warp & 1) * 64;

    float acc[2][8][4];
#pragma unroll
    for (int mt = 0; mt < 2; mt++)
#pragma unroll
        for (int nt = 0; nt < 8; nt++)
#pragma unroll
            for (int r = 0; r < 4; r++) acc[mt][nt][r] = 0.f;

    auto stage = [&](int ch, int buf) {
        float* dA = sA + buf * GA_FLOATS;
        float* dB = sB + buf * GB_FLOATS;
        const int c0 = ch * 32;
#pragma unroll
        for (int l = 0; l < 4; l++) {
            int idx = tid + l * 256;
            int row = idx >> 3, seg = (idx & 7) * 4;
            cpa16(dA + row * GA_PITCH + seg,
                  W + (size_t)(o0 + row) * 256 + c0 + seg);
        }
#pragma unroll
        for (int l = 0; l < 4; l++) {
            int idx = tid + l * 256;
            int row = idx >> 5, seg = (idx & 31) * 4;
            cpa16(dB + row * GB_PITCH + seg,
                  Xb + (size_t)(c0 + row) * HW + i0 + seg);
        }
    };

    stage(0, 0);
    CP_COMMIT;
    for (int ch = 0; ch < 8; ch++) {
        if (ch < 7) {
            stage(ch + 1, (ch + 1) & 1);
            CP_COMMIT;
            CP_WAIT(1);
        } else {
            CP_WAIT(0);
        }
        __syncthreads();
        const float* bA = sA + (ch & 1) * GA_FLOATS;
        const float* bB = sB + (ch & 1) * GB_FLOATS;
#pragma unroll
        for (int ks = 0; ks < 4; ks++) {
            float a[2][4];
#pragma unroll
            for (int mt = 0; mt < 2; mt++) {
                int r0 = wm + mt * 16 + g;
                a[mt][0] = bA[r0 * GA_PITCH + ks * 8 + t];
                a[mt][1] = bA[(r0 + 8) * GA_PITCH + ks * 8 + t];
                a[mt][2] = bA[r0 * GA_PITCH + ks * 8 + t + 4];
                a[mt][3] = bA[(r0 + 8) * GA_PITCH + ks * 8 + t + 4];
            }
#pragma unroll
            for (int nt = 0; nt < 8; nt++) {
                float b0 = bB[(ks * 8 + t) * GB_PITCH + wn + nt * 8 + g];
                float b1 = bB[(ks * 8 + t + 4) * GB_PITCH + wn + nt * 8 + g];
                mma_tf32(acc[0][nt], a[0], b0, b1);
                mma_tf32(acc[1][nt], a[1], b0, b1);
            }
        }
        __syncthreads();
    }

    // epilogue
#pragma unroll
    for (int mt = 0; mt < 2; mt++) {
#pragma unroll
        for (int nt = 0; nt < 8; nt++) {
            int row0 = o0 + wm + mt * 16 + g;
            int col = i0 + wn + nt * 8 + 2 * t;
            size_t a0 = (size_t)row0 * HW + col;
            size_t a1 = (size_t)(row0 + 8) * HW + col;
            float2 v0 = make_float2(acc[mt][nt][0], acc[mt][nt][1]);
            float2 v1 = make_float2(acc[mt][nt][2], acc[mt][nt][3]);
            if (EPI) {
                float add0 = bias[row0], add1 = bias[row0 + 8];
                float2 r0 = *(const float2*)&Rb[a0];
                float2 r1 = *(const float2*)&Rb[a1];
                v0.x += add0 + r0.x; v0.y += add0 + r0.y;
                v1.x += add1 + r1.x; v1.y += add1 + r1.y;
            }
            *(float2*)&Yb[a0] = v0;
            *(float2*)&Yb[a1] = v1;
        }
    }
}

// ================ Flash attention (tf32 mma, cp.async double-buffer) ========
// Grid (32, 16), 256 threads = 8 warps. Warp w owns Q rows [w*16, w*16+16).
#define SK_PITCH 136
#define SV_PITCH 132
#define SP_PITCH 132
#define SK_FLOATS (64 * SK_PITCH)
#define SV_FLOATS (64 * SV_PITCH)
#define SP_FLOATS (128 * SP_PITCH)
#define ATT_SMEM ((2 * SK_FLOATS + 2 * SV_FLOATS + SP_FLOATS) * sizeof(float))

__global__ __launch_bounds__(256, 1) void attn_k() {
    extern __shared__ float sm[];
    float* sK0 = sm;                              // [2][64][136]
    float* sV0 = sm + 2 * SK_FLOATS;              // [2][64][132]
    float* sP = sm + 2 * SK_FLOATS + 2 * SV_FLOATS;  // [128][132]
    float* sQst = sP;  // Q staging aliases sP (prologue only), pitch SK_PITCH

    const int bh = blockIdx.y;
    const int b = bh >> 2, h = bh & 3;
    const float* Qb = g_qkv + ((size_t)b * 768 + h * 64) * HW;
    const float* Kb = Qb + (size_t)256 * HW;
    const float* Vb = Qb + (size_t)512 * HW;
    const int i0 = blockIdx.x * 128;
    const int tid = threadIdx.x;
    const int warp = tid >> 5, lane = tid & 31;
    const int g = lane >> 2, t = lane & 3;
    const int iw = warp * 16;

    const float QSCALE = 0.125f * 1.4426950408889634f;  // d^-0.5 * log2(e)

    auto stage_kv = [&](int kt, int buf) {
        const float* Kt = Kb + kt * 128;
        const float* Vt = Vb + kt * 128;
        float* dK = sK0 + buf * SK_FLOATS;
        float* dV = sV0 + buf * SV_FLOATS;
        for (int e = tid * 4; e < 64 * 128; e += 1024) {
            int d = e >> 7, j = e & 127;
            cpa16(dK + d * SK_PITCH + j, Kt + (size_t)d * HW + j);
            cpa16(dV + d * SV_PITCH + j, Vt + (size_t)d * HW + j);
        }
    };

    // prefetch tile 0 while staging Q
    stage_kv(0, 0);
    CP_COMMIT;

    for (int e = tid * 4; e < 64 * 128; e += 1024) {
        int d = e >> 7, i = e & 127;
        float4 v = *(const float4*)&Qb[(size_t)d * HW + i0 + i];
        v.x = to_tf32(v.x * QSCALE); v.y = to_tf32(v.y * QSCALE);
        v.z = to_tf32(v.z * QSCALE); v.w = to_tf32(v.w * QSCALE);
        *(float4*)&sQst[d * SK_PITCH + i] = v;
    }
    __syncthreads();

    // persistent Q fragments
    float qa[8][4];
#pragma unroll
    for (int ks = 0; ks < 8; ks++) {
        qa[ks][0] = sQst[(ks * 8 + t) * SK_PITCH + iw + g];
        qa[ks][1] = sQst[(ks * 8 + t) * SK_PITCH + iw + g + 8];
        qa[ks][2] = sQst[(ks * 8 + t + 4) * SK_PITCH + iw + g];
        qa[ks][3] = sQst[(ks * 8 + t + 4) * SK_PITCH + iw + g + 8];
    }
    __syncthreads();  // done reading sQst (sP region reused below)

    float o[8][4];
#pragma unroll
    for (int dt = 0; dt < 8; dt++)
#pragma unroll
        for (int r = 0; r < 4; r++) o[dt][r] = 0.f;
    float m0 = -INFINITY, m1 = -INFINITY, l0 = 0.f, l1 = 0.f;

    for (int kt = 0; kt < 32; kt++) {
        if (kt + 1 < 32) {
            stage_kv(kt + 1, (kt + 1) & 1);
            CP_COMMIT;
            CP_WAIT(1);
        } else {
            CP_WAIT(0);
        }
        __syncthreads();
        const float* sK = sK0 + (kt & 1) * SK_FLOATS;
        const float* sV = sV0 + (kt & 1) * SV_FLOATS;

        // ---- S = Q K^T ----
        float c[16][4];
#pragma unroll
        for (int jt = 0; jt < 16; jt++)
#pragma unroll
            for (int r = 0; r < 4; r++) c[jt][r] = 0.f;
#pragma unroll
        for (int ks = 0; ks < 8; ks++) {
#pragma unroll
            for (int jt = 0; jt < 16; jt++) {
                float b0 = sK[(ks * 8 + t) * SK_PITCH + jt * 8 + g];
                float b1 = sK[(ks * 8 + t + 4) * SK_PITCH + jt * 8 + g];
                mma_tf32(c[jt], qa[ks], b0, b1);
            }
        }

        // ---- online softmax (log2 domain) ----
        float mx0 = c[0][0], mx1 = c[0][2];
#pragma unroll
        for (int jt = 0; jt < 16; jt++) {
            mx0 = fmaxf(mx0, fmaxf(c[jt][0], c[jt][1]));
            mx1 = fmaxf(mx1, fmaxf(c[jt][2], c[jt][3]));
        }
        mx0 = fmaxf(mx0, __shfl_xor_sync(0xffffffffu, mx0, 1));
        mx0 = fmaxf(mx0, __shfl_xor_sync(0xffffffffu, mx0, 2));
        mx1 = fmaxf(mx1, __shfl_xor_sync(0xffffffffu, mx1, 1));
        mx1 = fmaxf(mx1, __shfl_xor_sync(0xffffffffu, mx1, 2));
        float nm0 = fmaxf(m0, mx0), nm1 = fmaxf(m1, mx1);
        float r0 = ex2f(m0 - nm0), r1 = ex2f(m1 - nm1);
        float rs0 = 0.f, rs1 = 0.f;
#pragma unroll
        for (int jt = 0; jt < 16; jt++) {
            c[jt][0] = ex2f(c[jt][0] - nm0);
            c[jt][1] = ex2f(c[jt][1] - nm0);
            c[jt][2] = ex2f(c[jt][2] - nm1);
            c[jt][3] = ex2f(c[jt][3] - nm1);
            rs0 += c[jt][0] + c[jt][1];
            rs1 += c[jt][2] + c[jt][3];
        }
        rs0 += __shfl_xor_sync(0xffffffffu, rs0, 1);
        rs0 += __shfl_xor_sync(0xffffffffu, rs0, 2);
        rs1 += __shfl_xor_sync(0xffffffffu, rs1, 1);
        rs1 += __shfl_xor_sync(0xffffffffu, rs1, 2);
        l0 = l0 * r0 + rs0;
        l1 = l1 * r1 + rs1;
        m0 = nm0; m1 = nm1;
#pragma unroll
        for (int dt = 0; dt < 8; dt++) {
            o[dt][0] *= r0; o[dt][1] *= r0;
            o[dt][2] *= r1; o[dt][3] *= r1;
        }

        // ---- write P (tf32) to warp-private sP rows ----
#pragma unroll
        for (int jt = 0; jt < 16; jt++) {
            float2 p01 = make_float2(to_tf32(c[jt][0]), to_tf32(c[jt][1]));
            float2 p23 = make_float2(to_tf32(c[jt][2]), to_tf32(c[jt][3]));
            *(float2*)&sP[(iw + g) * SP_PITCH + jt * 8 + 2 * t] = p01;
            *(float2*)&sP[(iw + g + 8) * SP_PITCH + jt * 8 + 2 * t] = p23;
        }
        __syncwarp();

        // ---- O += P V ----
#pragma unroll 4
        for (int ks2 = 0; ks2 < 16; ks2++) {
            float a[4];
            a[0] = sP[(iw + g) * SP_PITCH + ks2 * 8 + t];
            a[1] = sP[(iw + g + 8) * SP_PITCH + ks2 * 8 + t];
            a[2] = sP[(iw + g) * SP_PITCH + ks2 * 8 + t + 4];
            a[3] = sP[(iw + g + 8) * SP_PITCH + ks2 * 8 + t + 4];
#pragma unroll
            for (int dt = 0; dt < 8; dt++) {
                float b0 = sV[(dt * 8 + g) * SV_PITCH + ks2 * 8 + t];
                float b1 = sV[(dt * 8 + g) * SV_PITCH + ks2 * 8 + t + 4];
                mma_tf32(o[dt], a, b0, b1);
            }
        }
        __syncthreads();
    }

    // ---- epilogue: O/l -> g_att ----
    float inv0 = 1.f / l0, inv1 = 1.f / l1;
    const size_t cb = ((size_t)b * 256 + h * 64);
#pragma unroll
    for (int dt = 0; dt < 8; dt++) {
        int d0 = dt * 8 + 2 * t;
        size_t r0a = (cb + d0) * HW + i0 + iw + g;
        size_t r1a = (cb + d0 + 1) * HW + i0 + iw + g;
        g_att[r0a] = o[dt][0] * inv0;
        g_att[r1a] = o[dt][1] * inv0;
        g_att[r0a + 8] = o[dt][2] * inv1;
        g_att[r1a + 8] = o[dt][3] * inv1;
    }
}

// ---------------- launch ----------------
extern "C" void kernel_launch(void* const* d_in, const int* in_sizes, int n_in,
                              void* d_out, int out_size) {
    (void)in_sizes; (void)n_in; (void)out_size;
    const float* x     = (const float*)d_in[0];
    const float* w_qkv = (const float*)d_in[1];
    const float* w_out = (const float*)d_in[2];
    const float* b_out = (const float*)d_in[3];
    float* out = (float*)d_out;

    float* qkv_p = nullptr;
    float* att_p = nullptr;
    cudaGetSymbolAddress((void**)&qkv_p, g_qkv);
    cudaGetSymbolAddress((void**)&att_p, g_att);

    cudaFuncSetAttribute(gemm_tc<768, false>,
                         cudaFuncAttributeMaxDynamicSharedMemorySize,
                         (int)GEMM_SMEM);
    cudaFuncSetAttribute(gemm_tc<256, true>,
                         cudaFuncAttributeMaxDynamicSharedMemorySize,
                         (int)GEMM_SMEM);
    cudaFuncSetAttribute(attn_k, cudaFuncAttributeMaxDynamicSharedMemorySize,
                         (int)ATT_SMEM);

    gemm_tc<768, false><<<dim3(32, 6, 4), 256, GEMM_SMEM>>>(w_qkv, x, nullptr,
                                                            nullptr, qkv_p);
    attn_k<<<dim3(32, 16), 256, ATT_SMEM>>>();
    gemm_tc<256, true><<<dim3(32, 2, 4), 256, GEMM_SMEM>>>(w_out, att_p, b_out,
                                                           x, out);
}